// round 12
// baseline (speedup 1.0000x reference)
#include <cuda_runtime.h>
#include <cuda_bf16.h>
#include <mma.h>
#include <cstdint>
#include <cstddef>

using namespace nvcuda;

// ---------------- problem constants ----------------
#define SEQ    512
#define BATCH  32
#define HID    1024
#define NSPAN  4096
#define DF     1024
#define VOC    32000
#define K1     2048
#define NB2    (VOC / 256)     // 125 N-tiles in gemm2 (CTA N = 256)
#define RBE    72              // smem row stride in bf16 elements (144 B)
#define ROWB   144             // row bytes
#define STAGE_B ((128 + 256) * ROWB)     // A(128 rows) + B(256 rows): 55296 B
#define GEMM_SMEM (STAGE_B * 2)          // 2 stages: 110592 B dynamic

// ---------------- scratch (device globals; NEVER passed as kernel args) ----------------
__device__ __nv_bfloat16 g_Woutb[(size_t)VOC * DF];     // 65.5 MB
__device__ __nv_bfloat16 g_W1b[(size_t)DF * K1];        // 4 MB
__device__ __nv_bfloat16 g_emb[(size_t)NSPAN * K1];     // 16 MB
__device__ __nv_bfloat16 g_feat[(size_t)NSPAN * DF];    // 8 MB
__device__ float g_partial[(size_t)NB2 * NSPAN];
__device__ float g_logit_tag[NSPAN];
__device__ float g_span_loss[NSPAN];
__device__ int g_tags[NSPAN];
__device__ int g_imax[4];
__device__ int g_sel[4];   // [0]=span_bid [1]=span_begin [2]=span_end_m1 [3]=tags

// ---------------- cp.async helpers ----------------
__device__ __forceinline__ void cp_async16(void* sdst, const void* gsrc) {
    asm volatile("cp.async.cg.shared.global [%0], [%1], 16;"
                 :: "l"(__cvta_generic_to_shared(sdst)),
                    "l"(__cvta_generic_to_global(gsrc)) : "memory");
}
#define CP_COMMIT() asm volatile("cp.async.commit_group;" ::: "memory")
__device__ __forceinline__ void cp_wait(int n) {
    if (n == 0) asm volatile("cp.async.wait_group 0;" ::: "memory");
    else        asm volatile("cp.async.wait_group 1;" ::: "memory");
}

// ---------------- int-quartet role detection ----------------
__global__ void __launch_bounds__(256) detect_max_kernel(
    const int* __restrict__ a0, const int* __restrict__ a1,
    const int* __restrict__ a2, const int* __restrict__ a3)
{
    const int* a = blockIdx.x == 0 ? a0 : blockIdx.x == 1 ? a1 : blockIdx.x == 2 ? a2 : a3;
    __shared__ int red[256];
    int t = threadIdx.x, m = 0;
    for (int i = t; i < NSPAN; i += 256) m = max(m, a[i]);
    red[t] = m;
    __syncthreads();
    for (int o = 128; o; o >>= 1) { if (t < o) red[t] = max(red[t], red[t + o]); __syncthreads(); }
    if (t == 0) g_imax[blockIdx.x] = red[0];
}

__global__ void perm_kernel() {
    int tagsi = 3, bidi = 0;
    for (int j = 0; j < 4; ++j) if (g_imax[j] >= 512) tagsi = j;
    for (int j = 0; j < 4; ++j) if (g_imax[j] < 32) bidi = j;
    int r0 = -1, r1 = -1;
    for (int j = 0; j < 4; ++j) if (j != tagsi && j != bidi) { if (r0 < 0) r0 = j; else r1 = j; }
    g_sel[0] = bidi; g_sel[1] = r0; g_sel[2] = r1; g_sel[3] = tagsi;
}

__global__ void __launch_bounds__(256) copy_tags_kernel(
    const int* __restrict__ a0, const int* __restrict__ a1,
    const int* __restrict__ a2, const int* __restrict__ a3)
{
    const int* arrs[4] = {a0, a1, a2, a3};
    const int* tags = arrs[g_sel[3]];
    int i = blockIdx.x * 256 + threadIdx.x;
    g_tags[i] = tags[i];
}

// ---------------- pre-convert kernels (dst = device global referenced IN DEVICE CODE) ----------------
__global__ void __launch_bounds__(256) cvt_wout_kernel(const float* __restrict__ src) {
    size_t i = ((size_t)blockIdx.x * 256 + threadIdx.x) * 8;
    float4 a = *(const float4*)(src + i);
    float4 b = *(const float4*)(src + i + 4);
    __nv_bfloat162* o = (__nv_bfloat162*)(g_Woutb + i);
    o[0] = __float22bfloat162_rn(make_float2(a.x, a.y));
    o[1] = __float22bfloat162_rn(make_float2(a.z, a.w));
    o[2] = __float22bfloat162_rn(make_float2(b.x, b.y));
    o[3] = __float22bfloat162_rn(make_float2(b.z, b.w));
}

__global__ void __launch_bounds__(256) cvt_w1_kernel(const float* __restrict__ src) {
    size_t i = ((size_t)blockIdx.x * 256 + threadIdx.x) * 8;
    float4 a = *(const float4*)(src + i);
    float4 b = *(const float4*)(src + i + 4);
    __nv_bfloat162* o = (__nv_bfloat162*)(g_W1b + i);
    o[0] = __float22bfloat162_rn(make_float2(a.x, a.y));
    o[1] = __float22bfloat162_rn(make_float2(a.z, a.w));
    o[2] = __float22bfloat162_rn(make_float2(b.x, b.y));
    o[3] = __float22bfloat162_rn(make_float2(b.z, b.w));
}

__global__ void __launch_bounds__(256) gather_kernel(
    const float* __restrict__ hidden,
    const int* __restrict__ a0, const int* __restrict__ a1,
    const int* __restrict__ a2, const int* __restrict__ a3)
{
    const int* arrs[4] = {a0, a1, a2, a3};
    const int* sbid = arrs[g_sel[0]];
    const int* sbeg = arrs[g_sel[1]];
    const int* send = arrs[g_sel[2]];
    int m = blockIdx.x;
    int b = sbid[m];
    const float* s0 = hidden + ((size_t)sbeg[m] * BATCH + b) * HID;
    const float* s1 = hidden + ((size_t)send[m] * BATCH + b) * HID;
    __nv_bfloat162* o = (__nv_bfloat162*)(g_emb + (size_t)m * K1);
    int c = threadIdx.x * 4;
    float4 v0 = *(const float4*)(s0 + c);
    float4 v1 = *(const float4*)(s1 + c);
    o[c / 2]             = __float22bfloat162_rn(make_float2(v0.x, v0.y));
    o[c / 2 + 1]         = __float22bfloat162_rn(make_float2(v0.z, v0.w));
    o[(HID + c) / 2]     = __float22bfloat162_rn(make_float2(v1.x, v1.y));
    o[(HID + c) / 2 + 1] = __float22bfloat162_rn(make_float2(v1.z, v1.w));
}

// ---------------- WMMA GEMM: CTA 128x256, warp 64x64 (2x4 grid), K-tile 64, 2-stage cp.async ----
// Operand pointers resolved IN DEVICE CODE from template flag (never host-passed). No reg cap.
template<bool IS_G1>
__global__ void __launch_bounds__(256) wmma_gemm_kernel(const float* __restrict__ b1)
{
    constexpr int KDIM = IS_G1 ? K1 : DF;
    constexpr int KT   = KDIM / 64;

    extern __shared__ __align__(16) char dsm[];
    const __nv_bfloat16* const Am = IS_G1 ? g_emb : g_feat;    // device-side symbol ref
    const __nv_bfloat16* const Bm = IS_G1 ? g_W1b : g_Woutb;

    const int tid = threadIdx.x, lane = tid & 31, w = tid >> 5;
    const int wm = w >> 2, wn = w & 3;          // warp grid 2 (m) x 4 (n); warp tile 64x64
    const int m0 = blockIdx.x * 128;
    const int n0 = blockIdx.y * 256;

    wmma::fragment<wmma::accumulator, 16, 16, 16, float> acc[4][4];
#pragma unroll
    for (int mi = 0; mi < 4; ++mi)
#pragma unroll
        for (int nj = 0; nj < 4; ++nj) wmma::fill_fragment(acc[mi][nj], 0.0f);

    auto load_stage = [&](int s, int kt) {
        char* sa = dsm + (uint32_t)s * STAGE_B;
        char* sb = sa + 128 * ROWB;
        const int kg = kt * 64;
#pragma unroll
        for (int i = 0; i < 4; ++i) {       // A: 128 rows x 128B
            int q = i * 256 + tid, row = q >> 3, c = q & 7;
            cp_async16(sa + row * ROWB + c * 16,
                       Am + (size_t)(m0 + row) * KDIM + kg + c * 8);
        }
#pragma unroll
        for (int i = 0; i < 8; ++i) {       // B: 256 rows x 128B
            int q = i * 256 + tid, row = q >> 3, c = q & 7;
            cp_async16(sb + row * ROWB + c * 16,
                       Bm + (size_t)(n0 + row) * KDIM + kg + c * 8);
        }
        CP_COMMIT();
    };

    load_stage(0, 0);

#pragma unroll 1
    for (int kt = 0; kt < KT; ++kt) {
        if (kt + 1 < KT) load_stage((kt + 1) & 1, kt + 1);
        cp_wait(kt + 1 < KT ? 1 : 0);       // stage kt complete (tail fully drains)
        __syncthreads();
        const __nv_bfloat16* sA = (const __nv_bfloat16*)(dsm + (uint32_t)(kt & 1) * STAGE_B);
        const __nv_bfloat16* sB = sA + 128 * RBE;
#pragma unroll
        for (int ks = 0; ks < 4; ++ks) {
            wmma::fragment<wmma::matrix_a, 16, 16, 16, __nv_bfloat16, wmma::row_major> fa;
            wmma::fragment<wmma::matrix_b, 16, 16, 16, __nv_bfloat16, wmma::col_major> fb[4];
#pragma unroll
            for (int nj = 0; nj < 4; ++nj)
                wmma::load_matrix_sync(fb[nj], &sB[(wn * 64 + nj * 16) * RBE + ks * 16], RBE);
#pragma unroll
            for (int mi = 0; mi < 4; ++mi) {
                wmma::load_matrix_sync(fa, &sA[(wm * 64 + mi * 16) * RBE + ks * 16], RBE);
#pragma unroll
                for (int nj = 0; nj < 4; ++nj)
                    wmma::mma_sync(acc[mi][nj], fa, fb[nj], acc[mi][nj]);
            }
        }
        __syncthreads();    // readers done before this buffer is overwritten (kt+2)
    }

    // epilogue scratch reuses stage memory (mainloop ended with syncthreads)
    float* scratch = (float*)dsm + w * (16 * 18);
    float* red     = (float*)dsm + 8 * (16 * 18);

    if (IS_G1) {
#pragma unroll 1
        for (int mi = 0; mi < 4; ++mi) {
#pragma unroll 1
            for (int nj = 0; nj < 4; ++nj) {
                wmma::store_matrix_sync(scratch, acc[mi][nj], 18, wmma::mem_row_major);
                __syncwarp();
                if (lane < 16) {
                    int row = m0 + wm * 64 + mi * 16 + lane;
                    int colb = n0 + wn * 64 + nj * 16;
#pragma unroll
                    for (int c = 0; c < 16; c += 2) {
                        float v0 = tanhf(scratch[lane * 18 + c]     + b1[colb + c]);
                        float v1 = tanhf(scratch[lane * 18 + c + 1] + b1[colb + c + 1]);
                        __nv_bfloat162 h = __float22bfloat162_rn(make_float2(v0, v1));
                        *(__nv_bfloat162*)(g_feat + (size_t)row * DF + colb + c) = h;
                    }
                }
                __syncwarp();
            }
        }
    } else {
#pragma unroll 1
        for (int mi = 0; mi < 4; ++mi) {
            float s = 0.0f;
            int row = m0 + wm * 64 + mi * 16 + (lane & 15);
            int tg = g_tags[row];
#pragma unroll 1
            for (int nj = 0; nj < 4; ++nj) {
                wmma::store_matrix_sync(scratch, acc[mi][nj], 18, wmma::mem_row_major);
                __syncwarp();
                if (lane < 16) {
                    int colb = n0 + wn * 64 + nj * 16;
#pragma unroll
                    for (int c = 0; c < 16; ++c) {
                        float v = scratch[lane * 18 + c];
                        s += __expf(v);
                        if (tg == colb + c) g_logit_tag[row] = v;
                    }
                }
                __syncwarp();
            }
            if (lane < 16) red[(wm * 64 + mi * 16 + lane) * 4 + wn] = s;
        }
        __syncthreads();
        if (tid < 128) {
            float t = red[tid * 4] + red[tid * 4 + 1] + red[tid * 4 + 2] + red[tid * 4 + 3];
            g_partial[(size_t)blockIdx.y * NSPAN + m0 + tid] = t;
        }
    }
}

// ---------------- per-span loss ----------------
__global__ void __launch_bounds__(256) span_loss_kernel(const float* __restrict__ discard)
{
    int l = blockIdx.x * 256 + threadIdx.x;
    float s = 0.0f;
#pragma unroll 5
    for (int nb = 0; nb < NB2; ++nb) s += g_partial[(size_t)nb * NSPAN + l];
    float nll = logf(s) - g_logit_tag[l];
    g_span_loss[l] = nll * (1.0f - discard[g_tags[l]]);
}

// ---------------- final deterministic reduction ----------------
__global__ void __launch_bounds__(1024) final_kernel(float* __restrict__ out) {
    __shared__ float red[1024];
    int t = threadIdx.x;
    float s = g_span_loss[t] + g_span_loss[t + 1024] + g_span_loss[t + 2048] + g_span_loss[t + 3072];
    red[t] = s;
    __syncthreads();
    for (int o = 512; o > 0; o >>= 1) {
        if (t < o) red[t] += red[t + o];
        __syncthreads();
    }
    if (t == 0) out[0] = red[0] / (4096.0f + 1e-5f);
}

// ---------------- launch ----------------
extern "C" void kernel_launch(void* const* d_in, const int* in_sizes, int n_in,
                              void* d_out, int out_size) {
    const float *hidden = nullptr, *W1 = nullptr, *b1 = nullptr, *Wout = nullptr, *discard = nullptr;
    const int* ia[4] = {nullptr, nullptr, nullptr, nullptr};
    int nints = 0;
    for (int i = 0; i < n_in; ++i) {
        switch (in_sizes[i]) {
            case 16777216: hidden  = (const float*)d_in[i]; break;   // S*B*H
            case 2097152:  W1      = (const float*)d_in[i]; break;   // D*2H
            case 1024:     b1      = (const float*)d_in[i]; break;   // D
            case 32768000: Wout    = (const float*)d_in[i]; break;   // V*D
            case 32000:    discard = (const float*)d_in[i]; break;   // V
            case 4096:     if (nints < 4) ia[nints++] = (const int*)d_in[i]; break;
            default: break;
        }
    }
    float* out = (float*)d_out;

    cudaFuncSetAttribute(wmma_gemm_kernel<true>,
                         cudaFuncAttributeMaxDynamicSharedMemorySize, GEMM_SMEM);
    cudaFuncSetAttribute(wmma_gemm_kernel<false>,
                         cudaFuncAttributeMaxDynamicSharedMemorySize, GEMM_SMEM);

    detect_max_kernel<<<4, 256>>>(ia[0], ia[1], ia[2], ia[3]);
    perm_kernel<<<1, 1>>>();
    copy_tags_kernel<<<16, 256>>>(ia[0], ia[1], ia[2], ia[3]);

    cvt_wout_kernel<<<16000, 256>>>(Wout);
    cvt_w1_kernel<<<1024, 256>>>(W1);
    gather_kernel<<<NSPAN, 256>>>(hidden, ia[0], ia[1], ia[2], ia[3]);

    // GEMM1: feat = tanh(emb @ W1^T + b1)   M=4096 N=1024 K=2048
    wmma_gemm_kernel<true><<<dim3(32, 4), 256, GEMM_SMEM>>>(b1);
    // GEMM2: logits + fused sum-exp         M=4096 N=32000 K=1024
    wmma_gemm_kernel<false><<<dim3(32, NB2), 256, GEMM_SMEM>>>(b1);

    span_loss_kernel<<<16, 256>>>(discard);
    final_kernel<<<1, 1024>>>(out);
}

// round 13
// speedup vs baseline: 2.5828x; 2.5828x over previous
#include <cuda_runtime.h>
#include <cuda_bf16.h>
#include <mma.h>
#include <cstdint>
#include <cstddef>

using namespace nvcuda;

// ---------------- problem constants ----------------
#define SEQ    512
#define BATCH  32
#define HID    1024
#define NSPAN  4096
#define DF     1024
#define VOC    32000
#define K1     2048
#define NB2    (VOC / 128)     // 250 N-tiles in gemm2
#define RBE    72              // smem row stride in bf16 elements (144 B)
#define STAGE_B (128 * RBE * 2 * 2)   // A + B tile, one stage: 36864 B
#define NSTAGE 3
#define GEMM_SMEM (STAGE_B * NSTAGE)  // 110592 B dynamic

// ---------------- scratch (device globals; NEVER passed as kernel args) ----------------
__device__ __nv_bfloat16 g_Woutb[(size_t)VOC * DF];     // 65.5 MB
__device__ __nv_bfloat16 g_W1b[(size_t)DF * K1];        // 4 MB
__device__ __nv_bfloat16 g_emb[(size_t)NSPAN * K1];     // 16 MB
__device__ __nv_bfloat16 g_feat[(size_t)NSPAN * DF];    // 8 MB
__device__ float g_partial[(size_t)NB2 * NSPAN];
__device__ float g_logit_tag[NSPAN];
__device__ float g_span_loss[NSPAN];
__device__ int g_tags[NSPAN];
__device__ int g_imax[4];
__device__ int g_sel[4];   // [0]=span_bid [1]=span_begin [2]=span_end_m1 [3]=tags

// ---------------- cp.async helpers ----------------
__device__ __forceinline__ void cp_async16(void* sdst, const void* gsrc) {
    asm volatile("cp.async.cg.shared.global [%0], [%1], 16;"
                 :: "l"(__cvta_generic_to_shared(sdst)),
                    "l"(__cvta_generic_to_global(gsrc)) : "memory");
}
#define CP_COMMIT() asm volatile("cp.async.commit_group;" ::: "memory")
__device__ __forceinline__ void cp_wait(int n) {
    if (n == 0) asm volatile("cp.async.wait_group 0;" ::: "memory");
    else        asm volatile("cp.async.wait_group 1;" ::: "memory");
}

// ---------------- int-quartet role detection ----------------
__global__ void __launch_bounds__(256) detect_max_kernel(
    const int* __restrict__ a0, const int* __restrict__ a1,
    const int* __restrict__ a2, const int* __restrict__ a3)
{
    const int* a = blockIdx.x == 0 ? a0 : blockIdx.x == 1 ? a1 : blockIdx.x == 2 ? a2 : a3;
    __shared__ int red[256];
    int t = threadIdx.x, m = 0;
    for (int i = t; i < NSPAN; i += 256) m = max(m, a[i]);
    red[t] = m;
    __syncthreads();
    for (int o = 128; o; o >>= 1) { if (t < o) red[t] = max(red[t], red[t + o]); __syncthreads(); }
    if (t == 0) g_imax[blockIdx.x] = red[0];
}

__global__ void perm_kernel() {
    int tagsi = 3, bidi = 0;
    for (int j = 0; j < 4; ++j) if (g_imax[j] >= 512) tagsi = j;
    for (int j = 0; j < 4; ++j) if (g_imax[j] < 32) bidi = j;
    int r0 = -1, r1 = -1;
    for (int j = 0; j < 4; ++j) if (j != tagsi && j != bidi) { if (r0 < 0) r0 = j; else r1 = j; }
    g_sel[0] = bidi; g_sel[1] = r0; g_sel[2] = r1; g_sel[3] = tagsi;
}

__global__ void __launch_bounds__(256) copy_tags_kernel(
    const int* __restrict__ a0, const int* __restrict__ a1,
    const int* __restrict__ a2, const int* __restrict__ a3)
{
    const int* arrs[4] = {a0, a1, a2, a3};
    const int* tags = arrs[g_sel[3]];
    int i = blockIdx.x * 256 + threadIdx.x;
    g_tags[i] = tags[i];
}

// ---------------- pre-convert kernels (dst = device global referenced IN DEVICE CODE) ----------------
__global__ void __launch_bounds__(256) cvt_wout_kernel(const float* __restrict__ src) {
    size_t i = ((size_t)blockIdx.x * 256 + threadIdx.x) * 8;
    float4 a = *(const float4*)(src + i);
    float4 b = *(const float4*)(src + i + 4);
    __nv_bfloat162* o = (__nv_bfloat162*)(g_Woutb + i);
    o[0] = __float22bfloat162_rn(make_float2(a.x, a.y));
    o[1] = __float22bfloat162_rn(make_float2(a.z, a.w));
    o[2] = __float22bfloat162_rn(make_float2(b.x, b.y));
    o[3] = __float22bfloat162_rn(make_float2(b.z, b.w));
}

__global__ void __launch_bounds__(256) cvt_w1_kernel(const float* __restrict__ src) {
    size_t i = ((size_t)blockIdx.x * 256 + threadIdx.x) * 8;
    float4 a = *(const float4*)(src + i);
    float4 b = *(const float4*)(src + i + 4);
    __nv_bfloat162* o = (__nv_bfloat162*)(g_W1b + i);
    o[0] = __float22bfloat162_rn(make_float2(a.x, a.y));
    o[1] = __float22bfloat162_rn(make_float2(a.z, a.w));
    o[2] = __float22bfloat162_rn(make_float2(b.x, b.y));
    o[3] = __float22bfloat162_rn(make_float2(b.z, b.w));
}

__global__ void __launch_bounds__(256) gather_kernel(
    const float* __restrict__ hidden,
    const int* __restrict__ a0, const int* __restrict__ a1,
    const int* __restrict__ a2, const int* __restrict__ a3)
{
    const int* arrs[4] = {a0, a1, a2, a3};
    const int* sbid = arrs[g_sel[0]];
    const int* sbeg = arrs[g_sel[1]];
    const int* send = arrs[g_sel[2]];
    int m = blockIdx.x;
    int b = sbid[m];
    const float* s0 = hidden + ((size_t)sbeg[m] * BATCH + b) * HID;
    const float* s1 = hidden + ((size_t)send[m] * BATCH + b) * HID;
    __nv_bfloat162* o = (__nv_bfloat162*)(g_emb + (size_t)m * K1);
    int c = threadIdx.x * 4;
    float4 v0 = *(const float4*)(s0 + c);
    float4 v1 = *(const float4*)(s1 + c);
    o[c / 2]             = __float22bfloat162_rn(make_float2(v0.x, v0.y));
    o[c / 2 + 1]         = __float22bfloat162_rn(make_float2(v0.z, v0.w));
    o[(HID + c) / 2]     = __float22bfloat162_rn(make_float2(v1.x, v1.y));
    o[(HID + c) / 2 + 1] = __float22bfloat162_rn(make_float2(v1.z, v1.w));
}

// ---------------- WMMA GEMM: CTA 128x128, warp 64x32, K-tile 64, 3-stage cp.async ----------------
// Prefetch distance 2; ONE barrier per K-tile (stage kt+2 never aliases stage kt or kt+1).
// Operand pointers resolved IN DEVICE CODE from template flag (never host-passed). No reg cap.
template<bool IS_G1>
__global__ void __launch_bounds__(256) wmma_gemm_kernel(const float* __restrict__ b1)
{
    constexpr int KDIM = IS_G1 ? K1 : DF;
    constexpr int KT   = KDIM / 64;

    extern __shared__ __align__(16) char dsm[];
    const __nv_bfloat16* const Am = IS_G1 ? g_emb : g_feat;    // device-side symbol ref
    const __nv_bfloat16* const Bm = IS_G1 ? g_W1b : g_Woutb;

    const int tid = threadIdx.x, lane = tid & 31, w = tid >> 5;
    const int wm = w >> 2, wn = w & 3;          // 2 x 4 warp grid; warp tile 64x32
    const int m0 = blockIdx.x * 128;
    const int n0 = blockIdx.y * 128;

    wmma::fragment<wmma::accumulator, 16, 16, 16, float> acc[4][2];
#pragma unroll
    for (int mi = 0; mi < 4; ++mi)
#pragma unroll
        for (int nj = 0; nj < 2; ++nj) wmma::fill_fragment(acc[mi][nj], 0.0f);

    auto load_stage = [&](int s, int kt) {
        char* sa = dsm + (uint32_t)s * STAGE_B;
        char* sb = sa + 128 * (RBE * 2);
        const int kg = kt * 64;
#pragma unroll
        for (int i = 0; i < 4; ++i) {       // A: 128 rows x 128B
            int q = i * 256 + tid, row = q >> 3, c = q & 7;
            cp_async16(sa + row * (RBE * 2) + c * 16,
                       Am + (size_t)(m0 + row) * KDIM + kg + c * 8);
        }
#pragma unroll
        for (int i = 0; i < 4; ++i) {       // B: 128 rows x 128B
            int q = i * 256 + tid, row = q >> 3, c = q & 7;
            cp_async16(sb + row * (RBE * 2) + c * 16,
                       Bm + (size_t)(n0 + row) * KDIM + kg + c * 8);
        }
        CP_COMMIT();
    };

    load_stage(0, 0);
    load_stage(1, 1);

#pragma unroll 1
    for (int kt = 0; kt < KT; ++kt) {
        cp_wait(kt + 1 < KT ? 1 : 0);       // stage kt's group complete (tail fully drains)
        __syncthreads();                    // all warps done reading stage (kt-1) == (kt+2)%3
        if (kt + 2 < KT) load_stage((kt + 2) % NSTAGE, kt + 2);
        const __nv_bfloat16* sA = (const __nv_bfloat16*)(dsm + (uint32_t)(kt % NSTAGE) * STAGE_B);
        const __nv_bfloat16* sB = sA + 128 * RBE;
#pragma unroll
        for (int ks = 0; ks < 4; ++ks) {
            wmma::fragment<wmma::matrix_a, 16, 16, 16, __nv_bfloat16, wmma::row_major> fa;
            wmma::fragment<wmma::matrix_b, 16, 16, 16, __nv_bfloat16, wmma::col_major> fb[2];
#pragma unroll
            for (int nj = 0; nj < 2; ++nj)
                wmma::load_matrix_sync(fb[nj], &sB[(wn * 32 + nj * 16) * RBE + ks * 16], RBE);
#pragma unroll
            for (int mi = 0; mi < 4; ++mi) {
                wmma::load_matrix_sync(fa, &sA[(wm * 64 + mi * 16) * RBE + ks * 16], RBE);
#pragma unroll
                for (int nj = 0; nj < 2; ++nj)
                    wmma::mma_sync(acc[mi][nj], fa, fb[nj], acc[mi][nj]);
            }
        }
    }
    __syncthreads();    // epilogue scratch aliases stage 0; ensure all warps exited mainloop

    // epilogue scratch reuses stage memory
    float* scratch = (float*)dsm + w * (16 * 18);
    float* red     = (float*)dsm + 8 * (16 * 18);

    if (IS_G1) {
#pragma unroll 1
        for (int mi = 0; mi < 4; ++mi) {
#pragma unroll 1
            for (int nj = 0; nj < 2; ++nj) {
                wmma::store_matrix_sync(scratch, acc[mi][nj], 18, wmma::mem_row_major);
                __syncwarp();
                if (lane < 16) {
                    int row = m0 + wm * 64 + mi * 16 + lane;
                    int colb = n0 + wn * 32 + nj * 16;
#pragma unroll
                    for (int c = 0; c < 16; c += 2) {
                        float v0 = tanhf(scratch[lane * 18 + c]     + b1[colb + c]);
                        float v1 = tanhf(scratch[lane * 18 + c + 1] + b1[colb + c + 1]);
                        __nv_bfloat162 h = __float22bfloat162_rn(make_float2(v0, v1));
                        *(__nv_bfloat162*)(g_feat + (size_t)row * DF + colb + c) = h;
                    }
                }
                __syncwarp();
            }
        }
    } else {
#pragma unroll 1
        for (int mi = 0; mi < 4; ++mi) {
            float s = 0.0f;
            int row = m0 + wm * 64 + mi * 16 + (lane & 15);
            int tg = g_tags[row];
#pragma unroll 1
            for (int nj = 0; nj < 2; ++nj) {
                wmma::store_matrix_sync(scratch, acc[mi][nj], 18, wmma::mem_row_major);
                __syncwarp();
                if (lane < 16) {
                    int colb = n0 + wn * 32 + nj * 16;
#pragma unroll
                    for (int c = 0; c < 16; ++c) {
                        float v = scratch[lane * 18 + c];
                        s += __expf(v);
                        if (tg == colb + c) g_logit_tag[row] = v;
                    }
                }
                __syncwarp();
            }
            if (lane < 16) red[(wm * 64 + mi * 16 + lane) * 4 + wn] = s;
        }
        __syncthreads();
        if (tid < 128) {
            float t = red[tid * 4] + red[tid * 4 + 1] + red[tid * 4 + 2] + red[tid * 4 + 3];
            g_partial[(size_t)blockIdx.y * NSPAN + m0 + tid] = t;
        }
    }
}

// ---------------- per-span loss ----------------
__global__ void __launch_bounds__(256) span_loss_kernel(const float* __restrict__ discard)
{
    int l = blockIdx.x * 256 + threadIdx.x;
    float s = 0.0f;
#pragma unroll 5
    for (int nb = 0; nb < NB2; ++nb) s += g_partial[(size_t)nb * NSPAN + l];
    float nll = logf(s) - g_logit_tag[l];
    g_span_loss[l] = nll * (1.0f - discard[g_tags[l]]);
}

// ---------------- final deterministic reduction ----------------
__global__ void __launch_bounds__(1024) final_kernel(float* __restrict__ out) {
    __shared__ float red[1024];
    int t = threadIdx.x;
    float s = g_span_loss[t] + g_span_loss[t + 1024] + g_span_loss[t + 2048] + g_span_loss[t + 3072];
    red[t] = s;
    __syncthreads();
    for (int o = 512; o > 0; o >>= 1) {
        if (t < o) red[t] += red[t + o];
        __syncthreads();
    }
    if (t == 0) out[0] = red[0] / (4096.0f + 1e-5f);
}

// ---------------- launch ----------------
extern "C" void kernel_launch(void* const* d_in, const int* in_sizes, int n_in,
                              void* d_out, int out_size) {
    const float *hidden = nullptr, *W1 = nullptr, *b1 = nullptr, *Wout = nullptr, *discard = nullptr;
    const int* ia[4] = {nullptr, nullptr, nullptr, nullptr};
    int nints = 0;
    for (int i = 0; i < n_in; ++i) {
        switch (in_sizes[i]) {
            case 16777216: hidden  = (const float*)d_in[i]; break;   // S*B*H
            case 2097152:  W1      = (const float*)d_in[i]; break;   // D*2H
            case 1024:     b1      = (const float*)d_in[i]; break;   // D
            case 32768000: Wout    = (const float*)d_in[i]; break;   // V*D
            case 32000:    discard = (const float*)d_in[i]; break;   // V
            case 4096:     if (nints < 4) ia[nints++] = (const int*)d_in[i]; break;
            default: break;
        }
    }
    float* out = (float*)d_out;

    cudaFuncSetAttribute(wmma_gemm_kernel<true>,
                         cudaFuncAttributeMaxDynamicSharedMemorySize, GEMM_SMEM);
    cudaFuncSetAttribute(wmma_gemm_kernel<false>,
                         cudaFuncAttributeMaxDynamicSharedMemorySize, GEMM_SMEM);

    detect_max_kernel<<<4, 256>>>(ia[0], ia[1], ia[2], ia[3]);
    perm_kernel<<<1, 1>>>();
    copy_tags_kernel<<<16, 256>>>(ia[0], ia[1], ia[2], ia[3]);

    cvt_wout_kernel<<<16000, 256>>>(Wout);
    cvt_w1_kernel<<<1024, 256>>>(W1);
    gather_kernel<<<NSPAN, 256>>>(hidden, ia[0], ia[1], ia[2], ia[3]);

    // GEMM1: feat = tanh(emb @ W1^T + b1)   M=4096 N=1024 K=2048
    wmma_gemm_kernel<true><<<dim3(32, 8), 256, GEMM_SMEM>>>(b1);
    // GEMM2: logits + fused sum-exp         M=4096 N=32000 K=1024
    wmma_gemm_kernel<false><<<dim3(32, NB2), 256, GEMM_SMEM>>>(b1);

    span_loss_kernel<<<16, 256>>>(discard);
    final_kernel<<<1, 1024>>>(out);
}

// round 14
// speedup vs baseline: 4.3044x; 1.6666x over previous
#include <cuda_runtime.h>
#include <cuda_fp16.h>
#include <mma.h>
#include <cstdint>
#include <cstddef>

using namespace nvcuda;

// ---------------- problem constants ----------------
#define SEQ    512
#define BATCH  32
#define HID    1024
#define NSPAN  4096
#define DF     1024
#define VOC    32000
#define K1     2048
#define NB2    (VOC / 256)     // 125 N-tiles in gemm2 (CTA N = 256)
#define RBE    72              // smem row stride in half elements (144 B)
#define ROWB   144
#define STAGE_B ((128 + 256) * ROWB)   // A(128 rows) + B(256 rows): 55296 B
#define GEMM_SMEM (STAGE_B * 2)        // 2 stages: 110592 B dynamic
#define SCR_LD 24                      // epilogue scratch stride (halfs)

// ---------------- scratch (device globals; NEVER passed as kernel args) ----------------
__device__ __half g_Wouth[(size_t)VOC * DF];     // 65.5 MB
__device__ __half g_W1h[(size_t)DF * K1];        // 4 MB
__device__ __half g_emb[(size_t)NSPAN * K1];     // 16 MB
__device__ __half g_feat[(size_t)NSPAN * DF];    // 8 MB
__device__ float g_partial[(size_t)NB2 * NSPAN];
__device__ float g_logit_tag[NSPAN];
__device__ float g_span_loss[NSPAN];
__device__ int g_tags[NSPAN];
__device__ int g_imax[4];
__device__ int g_sel[4];   // [0]=span_bid [1]=span_begin [2]=span_end_m1 [3]=tags

// ---------------- cp.async helpers ----------------
__device__ __forceinline__ void cp_async16(void* sdst, const void* gsrc) {
    asm volatile("cp.async.cg.shared.global [%0], [%1], 16;"
                 :: "l"(__cvta_generic_to_shared(sdst)),
                    "l"(__cvta_generic_to_global(gsrc)) : "memory");
}
#define CP_COMMIT() asm volatile("cp.async.commit_group;" ::: "memory")
__device__ __forceinline__ void cp_wait(int n) {
    if (n == 0) asm volatile("cp.async.wait_group 0;" ::: "memory");
    else        asm volatile("cp.async.wait_group 1;" ::: "memory");
}

// ---------------- int-quartet role detection ----------------
__global__ void __launch_bounds__(256) detect_max_kernel(
    const int* __restrict__ a0, const int* __restrict__ a1,
    const int* __restrict__ a2, const int* __restrict__ a3)
{
    const int* a = blockIdx.x == 0 ? a0 : blockIdx.x == 1 ? a1 : blockIdx.x == 2 ? a2 : a3;
    __shared__ int red[256];
    int t = threadIdx.x, m = 0;
    for (int i = t; i < NSPAN; i += 256) m = max(m, a[i]);
    red[t] = m;
    __syncthreads();
    for (int o = 128; o; o >>= 1) { if (t < o) red[t] = max(red[t], red[t + o]); __syncthreads(); }
    if (t == 0) g_imax[blockIdx.x] = red[0];
}

__global__ void perm_kernel() {
    int tagsi = 3, bidi = 0;
    for (int j = 0; j < 4; ++j) if (g_imax[j] >= 512) tagsi = j;
    for (int j = 0; j < 4; ++j) if (g_imax[j] < 32) bidi = j;
    int r0 = -1, r1 = -1;
    for (int j = 0; j < 4; ++j) if (j != tagsi && j != bidi) { if (r0 < 0) r0 = j; else r1 = j; }
    g_sel[0] = bidi; g_sel[1] = r0; g_sel[2] = r1; g_sel[3] = tagsi;
}

__global__ void __launch_bounds__(256) copy_tags_kernel(
    const int* __restrict__ a0, const int* __restrict__ a1,
    const int* __restrict__ a2, const int* __restrict__ a3)
{
    const int* arrs[4] = {a0, a1, a2, a3};
    const int* tags = arrs[g_sel[3]];
    int i = blockIdx.x * 256 + threadIdx.x;
    g_tags[i] = tags[i];
}

// ---------------- pre-convert kernels (dst = device global referenced IN DEVICE CODE) ----------------
__global__ void __launch_bounds__(256) cvt_wout_kernel(const float* __restrict__ src) {
    size_t i = ((size_t)blockIdx.x * 256 + threadIdx.x) * 8;
    float4 a = *(const float4*)(src + i);
    float4 b = *(const float4*)(src + i + 4);
    __half2* o = (__half2*)(g_Wouth + i);
    o[0] = __float22half2_rn(make_float2(a.x, a.y));
    o[1] = __float22half2_rn(make_float2(a.z, a.w));
    o[2] = __float22half2_rn(make_float2(b.x, b.y));
    o[3] = __float22half2_rn(make_float2(b.z, b.w));
}

__global__ void __launch_bounds__(256) cvt_w1_kernel(const float* __restrict__ src) {
    size_t i = ((size_t)blockIdx.x * 256 + threadIdx.x) * 8;
    float4 a = *(const float4*)(src + i);
    float4 b = *(const float4*)(src + i + 4);
    __half2* o = (__half2*)(g_W1h + i);
    o[0] = __float22half2_rn(make_float2(a.x, a.y));
    o[1] = __float22half2_rn(make_float2(a.z, a.w));
    o[2] = __float22half2_rn(make_float2(b.x, b.y));
    o[3] = __float22half2_rn(make_float2(b.z, b.w));
}

__global__ void __launch_bounds__(256) gather_kernel(
    const float* __restrict__ hidden,
    const int* __restrict__ a0, const int* __restrict__ a1,
    const int* __restrict__ a2, const int* __restrict__ a3)
{
    const int* arrs[4] = {a0, a1, a2, a3};
    const int* sbid = arrs[g_sel[0]];
    const int* sbeg = arrs[g_sel[1]];
    const int* send = arrs[g_sel[2]];
    int m = blockIdx.x;
    int b = sbid[m];
    const float* s0 = hidden + ((size_t)sbeg[m] * BATCH + b) * HID;
    const float* s1 = hidden + ((size_t)send[m] * BATCH + b) * HID;
    __half2* o = (__half2*)(g_emb + (size_t)m * K1);
    int c = threadIdx.x * 4;
    float4 v0 = *(const float4*)(s0 + c);
    float4 v1 = *(const float4*)(s1 + c);
    o[c / 2]             = __float22half2_rn(make_float2(v0.x, v0.y));
    o[c / 2 + 1]         = __float22half2_rn(make_float2(v0.z, v0.w));
    o[(HID + c) / 2]     = __float22half2_rn(make_float2(v1.x, v1.y));
    o[(HID + c) / 2 + 1] = __float22half2_rn(make_float2(v1.z, v1.w));
}

// ---------------- WMMA GEMM: CTA 128x256, warp 64x64 (2x4), K-tile 64, fp16 accum ----------------
// fp16 acc halves accumulator regs (no spill at 64x64) and halves fragment bytes/MAC.
// 2-stage cp.async (R10 structure). Operands via device-side symbols. No reg cap.
template<bool IS_G1>
__global__ void __launch_bounds__(256) wmma_gemm_kernel(const float* __restrict__ b1)
{
    constexpr int KDIM = IS_G1 ? K1 : DF;
    constexpr int KT   = KDIM / 64;

    extern __shared__ __align__(16) char dsm[];
    const __half* const Am = IS_G1 ? g_emb : g_feat;
    const __half* const Bm = IS_G1 ? g_W1h : g_Wouth;

    const int tid = threadIdx.x, lane = tid & 31, w = tid >> 5;
    const int wm = w >> 2, wn = w & 3;          // warp grid 2 (m) x 4 (n); warp tile 64x64
    const int m0 = blockIdx.x * 128;
    const int n0 = blockIdx.y * 256;

    wmma::fragment<wmma::accumulator, 16, 16, 16, __half> acc[4][4];
#pragma unroll
    for (int mi = 0; mi < 4; ++mi)
#pragma unroll
        for (int nj = 0; nj < 4; ++nj) wmma::fill_fragment(acc[mi][nj], __float2half(0.0f));

    auto load_stage = [&](int s, int kt) {
        char* sa = dsm + (uint32_t)s * STAGE_B;
        char* sb = sa + 128 * ROWB;
        const int kg = kt * 64;
#pragma unroll
        for (int i = 0; i < 4; ++i) {       // A: 128 rows x 128B
            int q = i * 256 + tid, row = q >> 3, c = q & 7;
            cp_async16(sa + row * ROWB + c * 16,
                       Am + (size_t)(m0 + row) * KDIM + kg + c * 8);
        }
#pragma unroll
        for (int i = 0; i < 8; ++i) {       // B: 256 rows x 128B
            int q = i * 256 + tid, row = q >> 3, c = q & 7;
            cp_async16(sb + row * ROWB + c * 16,
                       Bm + (size_t)(n0 + row) * KDIM + kg + c * 8);
        }
        CP_COMMIT();
    };

    load_stage(0, 0);

#pragma unroll 1
    for (int kt = 0; kt < KT; ++kt) {
        if (kt + 1 < KT) load_stage((kt + 1) & 1, kt + 1);
        cp_wait(kt + 1 < KT ? 1 : 0);       // stage kt complete (tail fully drains)
        __syncthreads();
        const __half* sA = (const __half*)(dsm + (uint32_t)(kt & 1) * STAGE_B);
        const __half* sB = sA + 128 * RBE;
#pragma unroll
        for (int ks = 0; ks < 4; ++ks) {
            wmma::fragment<wmma::matrix_a, 16, 16, 16, __half, wmma::row_major> fa;
            wmma::fragment<wmma::matrix_b, 16, 16, 16, __half, wmma::col_major> fb[4];
#pragma unroll
            for (int nj = 0; nj < 4; ++nj)
                wmma::load_matrix_sync(fb[nj], &sB[(wn * 64 + nj * 16) * RBE + ks * 16], RBE);
#pragma unroll
            for (int mi = 0; mi < 4; ++mi) {
                wmma::load_matrix_sync(fa, &sA[(wm * 64 + mi * 16) * RBE + ks * 16], RBE);
#pragma unroll
                for (int nj = 0; nj < 4; ++nj)
                    wmma::mma_sync(acc[mi][nj], fa, fb[nj], acc[mi][nj]);
            }
        }
        __syncthreads();    // readers done before buffer overwrite
    }

    // epilogue scratch reuses stage memory (mainloop ended with syncthreads)
    __half* scratch = (__half*)dsm + w * (16 * SCR_LD);
    float*  red     = (float*)((__half*)dsm + 8 * (16 * SCR_LD));

    if (IS_G1) {
#pragma unroll 1
        for (int mi = 0; mi < 4; ++mi) {
#pragma unroll 1
            for (int nj = 0; nj < 4; ++nj) {
                wmma::store_matrix_sync(scratch, acc[mi][nj], SCR_LD, wmma::mem_row_major);
                __syncwarp();
                if (lane < 16) {
                    int row = m0 + wm * 64 + mi * 16 + lane;
                    int colb = n0 + wn * 64 + nj * 16;
#pragma unroll
                    for (int c = 0; c < 16; c += 2) {
                        __half2 hv = *(__half2*)&scratch[lane * SCR_LD + c];
                        float2 fv = __half22float2(hv);
                        float v0 = tanhf(fv.x + b1[colb + c]);
                        float v1 = tanhf(fv.y + b1[colb + c + 1]);
                        *(__half2*)(g_feat + (size_t)row * DF + colb + c) =
                            __float22half2_rn(make_float2(v0, v1));
                    }
                }
                __syncwarp();
            }
        }
    } else {
#pragma unroll 1
        for (int mi = 0; mi < 4; ++mi) {
            float s = 0.0f;
            int row = m0 + wm * 64 + mi * 16 + (lane & 15);
            int tg = g_tags[row];
#pragma unroll 1
            for (int nj = 0; nj < 4; ++nj) {
                wmma::store_matrix_sync(scratch, acc[mi][nj], SCR_LD, wmma::mem_row_major);
                __syncwarp();
                if (lane < 16) {
                    int colb = n0 + wn * 64 + nj * 16;
#pragma unroll
                    for (int c = 0; c < 16; ++c) {
                        float v = __half2float(scratch[lane * SCR_LD + c]);
                        s += __expf(v);
                        if (tg == colb + c) g_logit_tag[row] = v;
                    }
                }
                __syncwarp();
            }
            if (lane < 16) red[(wm * 64 + mi * 16 + lane) * 4 + wn] = s;
        }
        __syncthreads();
        if (tid < 128) {
            float t = red[tid * 4] + red[tid * 4 + 1] + red[tid * 4 + 2] + red[tid * 4 + 3];
            g_partial[(size_t)blockIdx.y * NSPAN + m0 + tid] = t;
        }
    }
}

// ---------------- per-span loss ----------------
__global__ void __launch_bounds__(256) span_loss_kernel(const float* __restrict__ discard)
{
    int l = blockIdx.x * 256 + threadIdx.x;
    float s = 0.0f;
#pragma unroll 5
    for (int nb = 0; nb < NB2; ++nb) s += g_partial[(size_t)nb * NSPAN + l];
    float nll = logf(s) - g_logit_tag[l];
    g_span_loss[l] = nll * (1.0f - discard[g_tags[l]]);
}

// ---------------- final deterministic reduction ----------------
__global__ void __launch_bounds__(1024) final_kernel(float* __restrict__ out) {
    __shared__ float red[1024];
    int t = threadIdx.x;
    float s = g_span_loss[t] + g_span_loss[t + 1024] + g_span_loss[t + 2048] + g_span_loss[t + 3072];
    red[t] = s;
    __syncthreads();
    for (int o = 512; o > 0; o >>= 1) {
        if (t < o) red[t] += red[t + o];
        __syncthreads();
    }
    if (t == 0) out[0] = red[0] / (4096.0f + 1e-5f);
}

// ---------------- launch ----------------
extern "C" void kernel_launch(void* const* d_in, const int* in_sizes, int n_in,
                              void* d_out, int out_size) {
    const float *hidden = nullptr, *W1 = nullptr, *b1 = nullptr, *Wout = nullptr, *discard = nullptr;
    const int* ia[4] = {nullptr, nullptr, nullptr, nullptr};
    int nints = 0;
    for (int i = 0; i < n_in; ++i) {
        switch (in_sizes[i]) {
            case 16777216: hidden  = (const float*)d_in[i]; break;   // S*B*H
            case 2097152:  W1      = (const float*)d_in[i]; break;   // D*2H
            case 1024:     b1      = (const float*)d_in[i]; break;   // D
            case 32768000: Wout    = (const float*)d_in[i]; break;   // V*D
            case 32000:    discard = (const float*)d_in[i]; break;   // V
            case 4096:     if (nints < 4) ia[nints++] = (const int*)d_in[i]; break;
            default: break;
        }
    }
    float* out = (float*)d_out;

    cudaFuncSetAttribute(wmma_gemm_kernel<true>,
                         cudaFuncAttributeMaxDynamicSharedMemorySize, GEMM_SMEM);
    cudaFuncSetAttribute(wmma_gemm_kernel<false>,
                         cudaFuncAttributeMaxDynamicSharedMemorySize, GEMM_SMEM);

    detect_max_kernel<<<4, 256>>>(ia[0], ia[1], ia[2], ia[3]);
    perm_kernel<<<1, 1>>>();
    copy_tags_kernel<<<16, 256>>>(ia[0], ia[1], ia[2], ia[3]);

    cvt_wout_kernel<<<16000, 256>>>(Wout);
    cvt_w1_kernel<<<1024, 256>>>(W1);
    gather_kernel<<<NSPAN, 256>>>(hidden, ia[0], ia[1], ia[2], ia[3]);

    // GEMM1: feat = tanh(emb @ W1^T + b1)   M=4096 N=1024 K=2048
    wmma_gemm_kernel<true><<<dim3(32, 4), 256, GEMM_SMEM>>>(b1);
    // GEMM2: logits + fused sum-exp         M=4096 N=32000 K=1024
    wmma_gemm_kernel<false><<<dim3(32, NB2), 256, GEMM_SMEM>>>(b1);

    span_loss_kernel<<<16, 256>>>(discard);
    final_kernel<<<1, 1024>>>(out);
}